// round 5
// baseline (speedup 1.0000x reference)
#include <cuda_runtime.h>

#define KCL   64
#define PD    32
#define NBLK  296
#define TILE  512
#define DETC  1e-16f
#define NENT  2240

// ---- shared memory layout (bytes) ----
#define OFF_MUK2 0          // ull[32*32]  mu_k packed cluster-pairs [p][k2]   8192 B
#define OFF_ASM  8192       // 512 rows * 17 ull (mu_phi tile, pitch 34 fl)  69632 B
#define OFF_GR   77824      // 512 rows * 68 floats (gamma row-major)       139264 B
#define OFF_ECNA 217088     // ull[512]  (exp(lcp), ||x||^2) per point        4096 B
#define OFF_AK   221184     // float[64]  pi_k * exp(-16*lck)
#define OFF_ICOV 221440     // float[64]  exp(-lck)
#define OFF_NB   221696     // float[64]  ||mu_k||^2
#define SMEM_BYTES 221952

typedef unsigned long long ull;

// per-block partials, layout [block][entry]:
// 0..2047 = M[k][p], 2048..2111 = N_k, 2112..2175 = E_k, 2176..2239 = S2_k
__device__ float g_scratch[NBLK * NENT];
__device__ float g_acc[NENT];

__device__ __forceinline__ ull pk2(float lo, float hi) {
    ull u; asm("mov.b64 %0, {%1,%2};" : "=l"(u) : "f"(lo), "f"(hi)); return u;
}
__device__ __forceinline__ void upk2(ull u, float& lo, float& hi) {
    asm("mov.b64 {%0,%1}, %2;" : "=f"(lo), "=f"(hi) : "l"(u));
}
__device__ __forceinline__ ull fma2(ull a, ull b, ull c) {
    ull d; asm("fma.rn.f32x2 %0, %1, %2, %3;" : "=l"(d) : "l"(a), "l"(b), "l"(c));
    return d;
}

// E-step epilogue for one point: acc[k2] holds dot(x, mu_k) pairs; converts to
// gamma, writes row-major GR row (pitch 68 floats) with float4 stores.
#define EPILOGUE(ACC, NA, EC, VALID, GROW) do {                                \
    float tP_ = 32.0f * (EC);                                                  \
    float wsum_ = 0.0f;                                                        \
    _Pragma("unroll")                                                          \
    for (int k2 = 0; k2 < 32; ++k2) {                                          \
        float d0_, d1_; upk2(ACC[k2], d0_, d1_);                               \
        int k0_ = 2 * k2;                                                      \
        float sq0_ = (NA) - 2.0f * d0_ + NB[k0_];                              \
        float sq1_ = (NA) - 2.0f * d1_ + NB[k0_ + 1];                          \
        float w0_ = AK[k0_]     * __expf(-0.5f * ICOV[k0_]     * (tP_ + sq0_));\
        float w1_ = AK[k0_ + 1] * __expf(-0.5f * ICOV[k0_ + 1] * (tP_ + sq1_));\
        wsum_ += w0_ + w1_;                                                    \
        ACC[k2] = pk2(w0_, w1_);                                               \
    }                                                                          \
    float rs_ = (VALID) ? 1.0f / wsum_ : 0.0f;                                 \
    float dt_ = (VALID) ? DETC : 0.0f;                                         \
    ull rs2_ = pk2(rs_, rs_), dt2_ = pk2(dt_, dt_);                            \
    _Pragma("unroll")                                                          \
    for (int j = 0; j < 16; ++j) {                                             \
        ull h0_ = fma2(ACC[2 * j],     rs2_, dt2_);                            \
        ull h1_ = fma2(ACC[2 * j + 1], rs2_, dt2_);                            \
        float4 v_; upk2(h0_, v_.x, v_.y); upk2(h1_, v_.z, v_.w);               \
        *(float4*)((GROW) + 4 * j) = v_;                                       \
    }                                                                          \
} while (0)

__global__ __launch_bounds__(256, 1)
void deeplpm_main(const float* __restrict__ mu_phi,
                  const float* __restrict__ lcp_g,
                  const float* __restrict__ pi_k,
                  const float* __restrict__ mu_k,
                  const float* __restrict__ lck_g,
                  float* __restrict__ gamma_out,
                  int N) {
    extern __shared__ unsigned char sm[];
    ull*   MUK2 = (ull*)(sm + OFF_MUK2);
    float* ASMf = (float*)(sm + OFF_ASM);   // pitch 34 floats per point
    ull*   ASMu = (ull*)(sm + OFF_ASM);     // pitch 17 ull per point
    float* GRf  = (float*)(sm + OFF_GR);    // pitch 68 floats per point
    ull*   ECNA = (ull*)(sm + OFF_ECNA);
    float* AK   = (float*)(sm + OFF_AK);
    float* ICOV = (float*)(sm + OFF_ICOV);
    float* NB   = (float*)(sm + OFF_NB);

    const int tid = threadIdx.x;

    // ---- init tables ----
    for (int idx = tid; idx < 1024; idx += 256) {
        int k2 = idx & 31, p = idx >> 5;
        MUK2[p * 32 + k2] = pk2(mu_k[(2 * k2) * PD + p], mu_k[(2 * k2 + 1) * PD + p]);
    }
    if (tid < KCL) {
        float lck = lck_g[tid];
        ICOV[tid] = __expf(-lck);
        AK[tid]   = pi_k[tid] * __expf(-16.0f * lck);
        float nb = 0.0f;
        #pragma unroll
        for (int p = 0; p < PD; ++p) { float v = mu_k[tid * PD + p]; nb = fmaf(v, v, nb); }
        NB[tid] = nb;
    }

    // GEMM2 roles: 8 point-groups (q3) x 16 cluster-quads (c4) x 2 p-halves (ph)
    const int q3 = tid >> 5;
    const int c4 = (tid & 31) >> 1;
    const int ph = tid & 1;

    ull macc[4][8];
    #pragma unroll
    for (int c = 0; c < 4; ++c)
        #pragma unroll
        for (int j = 0; j < 8; ++j) macc[c][j] = 0ull;
    float nacc[4] = {0.f, 0.f, 0.f, 0.f};
    ull es2[4] = {0ull, 0ull, 0ull, 0ull};

    const int tiles = (N + TILE - 1) / TILE;

    for (int tile = blockIdx.x; tile < tiles; tile += gridDim.x) {
        __syncthreads();   // previous iteration's readers done before overwrite
        const int t0 = tile * TILE;
        int vpts = N - t0; if (vpts > TILE) vpts = TILE;
        const int vflt = vpts * PD;

        // ---- coalesced load mu_phi tile -> ASM (pitch 34 floats) ----
        {
            const float* src = mu_phi + (size_t)t0 * PD;
            #pragma unroll
            for (int c = 0; c < 16; ++c) {
                int idx = c * 1024 + tid * 4;
                float4 v = make_float4(0.f, 0.f, 0.f, 0.f);
                if (idx < vflt) v = *(const float4*)(src + idx);
                float* d = ASMf + (idx >> 5) * 34 + (idx & 31);
                ((float2*)d)[0] = make_float2(v.x, v.y);
                ((float2*)d)[1] = make_float2(v.z, v.w);
            }
        }
        const int iA = t0 + tid, iB = iA + 256;
        const bool vA = iA < N, vB = iB < N;
        const float ecA = vA ? __expf(lcp_g[iA]) : 0.f;
        const float ecB = vB ? __expf(lcp_g[iB]) : 0.f;
        __syncthreads();

        // ---- GEMM1: 2 points/thread, MUK2 LDS amortized over both ----
        ull accA[32], accB[32];
        #pragma unroll
        for (int k2 = 0; k2 < 32; ++k2) { accA[k2] = 0ull; accB[k2] = 0ull; }
        ull na2 = 0ull;
        const float* rowA = ASMf + tid * 34;
        const float* rowB = ASMf + (tid + 256) * 34;
        #pragma unroll 4
        for (int pp = 0; pp < 16; ++pp) {
            float2 fa = *(const float2*)(rowA + 2 * pp);
            float2 fb = *(const float2*)(rowB + 2 * pp);
            {
                ull a2A = pk2(fa.x, fa.x), a2B = pk2(fb.x, fb.x);
                ull nab = pk2(fa.x, fb.x);
                na2 = fma2(nab, nab, na2);
                const ull* mk = MUK2 + (2 * pp) * 32;
                #pragma unroll
                for (int k2 = 0; k2 < 32; ++k2) {
                    ull m = mk[k2];
                    accA[k2] = fma2(a2A, m, accA[k2]);
                    accB[k2] = fma2(a2B, m, accB[k2]);
                }
            }
            {
                ull a2A = pk2(fa.y, fa.y), a2B = pk2(fb.y, fb.y);
                ull nab = pk2(fa.y, fb.y);
                na2 = fma2(nab, nab, na2);
                const ull* mk = MUK2 + (2 * pp + 1) * 32;
                #pragma unroll
                for (int k2 = 0; k2 < 32; ++k2) {
                    ull m = mk[k2];
                    accA[k2] = fma2(a2A, m, accA[k2]);
                    accB[k2] = fma2(a2B, m, accB[k2]);
                }
            }
        }
        float naA, naB; upk2(na2, naA, naB);

        // ---- E-step epilogue: gamma rows into GR (row-major) ----
        EPILOGUE(accA, naA, ecA, vA, GRf + tid * 68);
        EPILOGUE(accB, naB, ecB, vB, GRf + (tid + 256) * 68);
        ECNA[tid]       = pk2(ecA, naA);
        ECNA[tid + 256] = pk2(ecB, naB);
        __syncthreads();

        // ---- coalesced gamma store: GR -> global (contiguous tile) ----
        {
            float* gdst = gamma_out + (size_t)t0 * KCL;
            const int vf = vpts * KCL;
            #pragma unroll
            for (int c = 0; c < 32; ++c) {
                int o = (c * 256 + tid) * 4;
                if (o < vf) {
                    const float* s = GRf + (o >> 6) * 68 + (o & 63);
                    *(float4*)(gdst + o) = *(const float4*)s;
                }
            }
        }

        // ---- GEMM2: 4 clusters/thread; arow LDS reused by 32 FFMA2 ----
        {
            const int pb = q3 * 64;
            #pragma unroll 2
            for (int u = 0; u < 64; ++u) {
                const int pt = pb + u;
                ull ar[8];
                const ull* arow = ASMu + pt * 17 + ph * 8;
                #pragma unroll
                for (int j = 0; j < 8; ++j) ar[j] = arow[j];
                float4 g4 = *(const float4*)(GRf + pt * 68 + c4 * 4);
                float gg[4] = {g4.x, g4.y, g4.z, g4.w};
                #pragma unroll
                for (int c = 0; c < 4; ++c) {
                    ull g2 = pk2(gg[c], gg[c]);
                    #pragma unroll
                    for (int j = 0; j < 8; ++j)
                        macc[c][j] = fma2(g2, ar[j], macc[c][j]);
                }
                if (ph == 0) {
                    ull en = ECNA[pt];
                    #pragma unroll
                    for (int c = 0; c < 4; ++c) {
                        nacc[c] += gg[c];
                        es2[c] = fma2(pk2(gg[c], gg[c]), en, es2[c]);
                    }
                }
            }
        }
    }

    // ---- combine partials across the 8 point-groups (reuse smem) ----
    __syncthreads();
    ull*   SB = (ull*)sm;                    // 256*32 ull = 64 KB
    float* SN = (float*)(sm + 65536);        // 512 floats
    float* SE = SN + 512;
    float* SS = SE + 512;
    #pragma unroll
    for (int c = 0; c < 4; ++c)
        #pragma unroll
        for (int j = 0; j < 8; ++j)
            SB[tid * 32 + c * 8 + j] = macc[c][j];
    if (ph == 0) {
        int b = q3 * 64 + c4 * 4;
        #pragma unroll
        for (int c = 0; c < 4; ++c) {
            float e, s; upk2(es2[c], e, s);
            SN[b + c] = nacc[c]; SE[b + c] = e; SS[b + c] = s;
        }
    }
    __syncthreads();

    float* my = g_scratch + (size_t)blockIdx.x * NENT;
    for (int o = tid; o < 1024; o += 256) {
        int k = o >> 4, jp = o & 15;
        int cc = k >> 2, c = k & 3, hh = jp >> 3, j = jp & 7;
        float s0 = 0.f, s1 = 0.f;
        #pragma unroll
        for (int q = 0; q < 8; ++q) {
            float x0, x1;
            upk2(SB[((q << 5) | (cc << 1) | hh) * 32 + c * 8 + j], x0, x1);
            s0 += x0; s1 += x1;
        }
        my[k * PD + 2 * jp]     = s0;
        my[k * PD + 2 * jp + 1] = s1;
    }
    if (tid < KCL) {
        float n = 0.f, e = 0.f, s = 0.f;
        #pragma unroll
        for (int q = 0; q < 8; ++q) {
            n += SN[q * 64 + tid]; e += SE[q * 64 + tid]; s += SS[q * 64 + tid];
        }
        my[2048 + tid] = n;
        my[2112 + tid] = e;
        my[2176 + tid] = s;
    }
}

// Stage 1: reduce g_scratch[nblk][NENT] -> g_acc[NENT], coalesced + MLP=4.
__global__ __launch_bounds__(256)
void deeplpm_reduce(int nblk) {
    int e = blockIdx.x * 256 + threadIdx.x;
    if (e >= NENT) return;
    const float* p = g_scratch + e;
    float s0 = 0.f, s1 = 0.f, s2 = 0.f, s3 = 0.f;
    int b = 0;
    for (; b + 4 <= nblk; b += 4) {
        s0 += p[(size_t)(b + 0) * NENT];
        s1 += p[(size_t)(b + 1) * NENT];
        s2 += p[(size_t)(b + 2) * NENT];
        s3 += p[(size_t)(b + 3) * NENT];
    }
    for (; b < nblk; ++b) s0 += p[(size_t)b * NENT];
    g_acc[e] = (s0 + s1) + (s2 + s3);
}

// Stage 2: final per-cluster math.
__global__ __launch_bounds__(64)
void deeplpm_finalize(float* __restrict__ pi_out,
                      float* __restrict__ mu_out,
                      float* __restrict__ lc_out,
                      int N) {
    int t = threadIdx.x;
    if (t >= KCL) return;
    float Nk = g_acc[2048 + t];
    float Ek = g_acc[2112 + t];
    float Sk = g_acc[2176 + t];
    pi_out[t] = Nk / (float)N;
    float inv = 1.0f / Nk;
    float nm2 = 0.0f;
    #pragma unroll
    for (int p = 0; p < PD; ++p) {
        float m = g_acc[t * PD + p] * inv;
        mu_out[t * PD + p] = m;
        nm2 = fmaf(m, m, nm2);
    }
    float cov = (32.0f * Ek + Sk - Nk * nm2) / (32.0f * Nk);
    lc_out[t] = logf(cov);
}

extern "C" void kernel_launch(void* const* d_in, const int* in_sizes, int n_in,
                              void* d_out, int out_size) {
    const float* mu_phi = (const float*)d_in[0];
    const float* lcp    = (const float*)d_in[1];
    const float* pi_k   = (const float*)d_in[2];
    const float* mu_k   = (const float*)d_in[3];
    const float* lck    = (const float*)d_in[4];
    const int N = in_sizes[0] / PD;

    float* out     = (float*)d_out;
    float* gamma_o = out;
    float* pi_o    = out + (size_t)N * KCL;
    float* mu_o    = pi_o + KCL;
    float* lc_o    = mu_o + KCL * PD;

    int tiles = (N + TILE - 1) / TILE;
    int grid  = tiles < NBLK ? tiles : NBLK;

    cudaFuncSetAttribute(deeplpm_main,
                         cudaFuncAttributeMaxDynamicSharedMemorySize, SMEM_BYTES);

    deeplpm_main<<<grid, 256, SMEM_BYTES>>>(mu_phi, lcp, pi_k, mu_k, lck,
                                            gamma_o, N);
    deeplpm_reduce<<<(NENT + 255) / 256, 256>>>(grid);
    deeplpm_finalize<<<1, 64>>>(pi_o, mu_o, lc_o, N);
}

// round 6
// speedup vs baseline: 1.1627x; 1.1627x over previous
#include <cuda_runtime.h>

#define KCL   64
#define PD    32
#define NBLK  296
#define TILE  256
#define DETC  1e-16f
#define NENT  2240

typedef unsigned long long ull;

// ---- shared memory layout (bytes) ----
#define OFF_MUK2 0          // ull[32*32]  mu_k cluster-pairs [p][pair]        8192 B
#define OFF_ASM  8192       // 256 rows * 18 ull (mu_phi tile, pitch 36 fl)  36864 B
#define OFF_GR   45056      // 256 rows * 72 floats (gamma row-major)        73728 B
#define OFF_EC   118784     // float[256] exp(lcp)
#define OFF_NA   119808     // float[256] ||x||^2
#define OFF_AK   120832     // float[64]  pi_k * exp(-16*lck)
#define OFF_ICOV 121088     // float[64]  exp(-lck)
#define OFF_NB   121344     // float[64]  ||mu_k||^2
#define SMEM_BYTES 121600

// per-block partials, layout [block][entry]:
// 0..2047 = M[k][p], 2048..2111 = N_k, 2112..2175 = E_k, 2176..2239 = S2_k
__device__ float g_scratch[NBLK * NENT];
__device__ float g_acc[NENT];

__device__ __forceinline__ ull pk2(float lo, float hi) {
    ull u; asm("mov.b64 %0, {%1,%2};" : "=l"(u) : "f"(lo), "f"(hi)); return u;
}
__device__ __forceinline__ void upk2(ull u, float& lo, float& hi) {
    asm("mov.b64 {%0,%1}, %2;" : "=f"(lo), "=f"(hi) : "l"(u));
}
__device__ __forceinline__ ull fma2(ull a, ull b, ull c) {
    ull d; asm("fma.rn.f32x2 %0, %1, %2, %3;" : "=l"(d) : "l"(a), "l"(b), "l"(c));
    return d;
}

__global__ __launch_bounds__(256, 1)
void deeplpm_main(const float* __restrict__ mu_phi,
                  const float* __restrict__ lcp_g,
                  const float* __restrict__ pi_k,
                  const float* __restrict__ mu_k,
                  const float* __restrict__ lck_g,
                  float* __restrict__ gamma_out,
                  int N) {
    extern __shared__ unsigned char sm[];
    ull*   MUK2 = (ull*)(sm + OFF_MUK2);
    float* ASMf = (float*)(sm + OFF_ASM);   // pitch 36 floats per point
    ull*   ASMu = (ull*)(sm + OFF_ASM);     // pitch 18 ull per point
    float* GRf  = (float*)(sm + OFF_GR);    // pitch 72 floats, col = cluster k
    float* ECs  = (float*)(sm + OFF_EC);
    float* NAs  = (float*)(sm + OFF_NA);
    float* AK   = (float*)(sm + OFF_AK);
    float* ICOV = (float*)(sm + OFF_ICOV);
    float* NB   = (float*)(sm + OFF_NB);

    const int tid = threadIdx.x;

    // ---- init tables ----
    for (int idx = tid; idx < 1024; idx += 256) {
        int pr = idx & 31, p = idx >> 5;
        MUK2[p * 32 + pr] = pk2(mu_k[(2 * pr) * PD + p], mu_k[(2 * pr + 1) * PD + p]);
    }
    if (tid < KCL) {
        float lck = lck_g[tid];
        ICOV[tid] = __expf(-lck);
        AK[tid]   = pi_k[tid] * __expf(-16.0f * lck);
        float nb = 0.0f;
        #pragma unroll
        for (int p = 0; p < PD; ++p) { float v = mu_k[tid * PD + p]; nb = fmaf(v, v, nb); }
        NB[tid] = nb;
    }

    // GEMM1 roles: 64 point-quads (g) x 4 cluster-splits (s, 16 clusters each)
    const int s  = tid & 3;
    const int g  = tid >> 2;
    // GEMM2 roles: 8 point-groups (q3, 32 pts) x 16 cluster-quads (c4) x p-half (ph)
    const int q3 = tid >> 5;
    const int c4 = (tid & 31) >> 1;
    const int ph = tid & 1;

    ull macc[4][8];
    #pragma unroll
    for (int c = 0; c < 4; ++c)
        #pragma unroll
        for (int j = 0; j < 8; ++j) macc[c][j] = 0ull;
    float nacc[4] = {0.f, 0.f, 0.f, 0.f};
    ull es2[4] = {0ull, 0ull, 0ull, 0ull};

    const int tiles = (N + TILE - 1) / TILE;

    for (int tile = blockIdx.x; tile < tiles; tile += gridDim.x) {
        __syncthreads();   // previous iteration's readers done before overwrite
        const int t0 = tile * TILE;
        int vpts = N - t0; if (vpts > TILE) vpts = TILE;
        const int vflt = vpts * PD;

        // ---- coalesced stage: mu_phi tile -> ASM (pitch 36 fl), exp(lcp) -> ECs
        {
            const float* src = mu_phi + (size_t)t0 * PD;
            #pragma unroll
            for (int c = 0; c < 8; ++c) {
                int idx = c * 1024 + tid * 4;
                float4 v = make_float4(0.f, 0.f, 0.f, 0.f);
                if (idx < vflt) v = *(const float4*)(src + idx);
                *(float4*)(ASMf + (idx >> 5) * 36 + (idx & 31)) = v;
            }
            int i = t0 + tid;
            ECs[tid] = (i < N) ? __expf(lcp_g[i]) : 0.f;
        }
        __syncthreads();

        // ---- GEMM1: 4 points x 16 clusters per thread ----
        ull acc[4][8];
        #pragma unroll
        for (int i = 0; i < 4; ++i)
            #pragma unroll
            for (int j = 0; j < 8; ++j) acc[i][j] = 0ull;
        ull na01 = 0ull, na23 = 0ull;

        const float* r0 = ASMf + (4 * g + 0) * 36;
        const float* r1 = ASMf + (4 * g + 1) * 36;
        const float* r2 = ASMf + (4 * g + 2) * 36;
        const float* r3 = ASMf + (4 * g + 3) * 36;
        const ull* mkbase = MUK2 + 8 * s;

        #pragma unroll 4
        for (int pp = 0; pp < 16; ++pp) {
            float2 f0 = *(const float2*)(r0 + 2 * pp);
            float2 f1 = *(const float2*)(r1 + 2 * pp);
            float2 f2 = *(const float2*)(r2 + 2 * pp);
            float2 f3 = *(const float2*)(r3 + 2 * pp);
            {
                ull t01 = pk2(f0.x, f1.x), t23 = pk2(f2.x, f3.x);
                na01 = fma2(t01, t01, na01);
                na23 = fma2(t23, t23, na23);
            }
            {
                ull t01 = pk2(f0.y, f1.y), t23 = pk2(f2.y, f3.y);
                na01 = fma2(t01, t01, na01);
                na23 = fma2(t23, t23, na23);
            }
            // p = 2*pp
            {
                const ulonglong2* mk = (const ulonglong2*)(mkbase + (2 * pp) * 32);
                ulonglong2 m0 = mk[0], m1 = mk[1], m2 = mk[2], m3 = mk[3];
                ull m[8] = {m0.x, m0.y, m1.x, m1.y, m2.x, m2.y, m3.x, m3.y};
                ull x0 = pk2(f0.x, f0.x), x1 = pk2(f1.x, f1.x);
                ull x2 = pk2(f2.x, f2.x), x3 = pk2(f3.x, f3.x);
                #pragma unroll
                for (int j = 0; j < 8; ++j) {
                    acc[0][j] = fma2(x0, m[j], acc[0][j]);
                    acc[1][j] = fma2(x1, m[j], acc[1][j]);
                    acc[2][j] = fma2(x2, m[j], acc[2][j]);
                    acc[3][j] = fma2(x3, m[j], acc[3][j]);
                }
            }
            // p = 2*pp + 1
            {
                const ulonglong2* mk = (const ulonglong2*)(mkbase + (2 * pp + 1) * 32);
                ulonglong2 m0 = mk[0], m1 = mk[1], m2 = mk[2], m3 = mk[3];
                ull m[8] = {m0.x, m0.y, m1.x, m1.y, m2.x, m2.y, m3.x, m3.y};
                ull x0 = pk2(f0.y, f0.y), x1 = pk2(f1.y, f1.y);
                ull x2 = pk2(f2.y, f2.y), x3 = pk2(f3.y, f3.y);
                #pragma unroll
                for (int j = 0; j < 8; ++j) {
                    acc[0][j] = fma2(x0, m[j], acc[0][j]);
                    acc[1][j] = fma2(x1, m[j], acc[1][j]);
                    acc[2][j] = fma2(x2, m[j], acc[2][j]);
                    acc[3][j] = fma2(x3, m[j], acc[3][j]);
                }
            }
        }
        float na[4];
        upk2(na01, na[0], na[1]);
        upk2(na23, na[2], na[3]);
        if (s == 0) {
            #pragma unroll
            for (int i = 0; i < 4; ++i) NAs[4 * g + i] = na[i];
        }

        // ---- epilogue: w for this thread's 16 clusters, per-point ----
        float ws[4];
        #pragma unroll
        for (int i = 0; i < 4; ++i) {
            float ec = ECs[4 * g + i];
            float tP = 32.0f * ec;
            float w_ = 0.0f;
            #pragma unroll
            for (int j = 0; j < 8; ++j) {
                int k0 = 16 * s + 2 * j;
                float d0, d1; upk2(acc[i][j], d0, d1);
                float sq0 = na[i] - 2.0f * d0 + NB[k0];
                float sq1 = na[i] - 2.0f * d1 + NB[k0 + 1];
                float w0 = AK[k0]     * __expf(-0.5f * ICOV[k0]     * (tP + sq0));
                float w1 = AK[k0 + 1] * __expf(-0.5f * ICOV[k0 + 1] * (tP + sq1));
                w_ += w0 + w1;
                acc[i][j] = pk2(w0, w1);
            }
            ws[i] = w_;
        }
        // cross-split reduction of wsum (4 lanes per point-quad)
        #pragma unroll
        for (int i = 0; i < 4; ++i) {
            ws[i] += __shfl_xor_sync(0xffffffffu, ws[i], 1);
            ws[i] += __shfl_xor_sync(0xffffffffu, ws[i], 2);
        }
        // gamma = w/wsum + DET -> GR rows (col = global cluster index)
        #pragma unroll
        for (int i = 0; i < 4; ++i) {
            bool valid = (t0 + 4 * g + i) < N;
            float rs = valid ? 1.0f / ws[i] : 0.0f;
            float dt = valid ? DETC : 0.0f;
            ull rs2 = pk2(rs, rs), dt2 = pk2(dt, dt);
            float* grow = GRf + (4 * g + i) * 72 + 16 * s;
            #pragma unroll
            for (int q = 0; q < 4; ++q) {
                ull h0 = fma2(acc[i][2 * q],     rs2, dt2);
                ull h1 = fma2(acc[i][2 * q + 1], rs2, dt2);
                float4 v; upk2(h0, v.x, v.y); upk2(h1, v.z, v.w);
                *(float4*)(grow + 4 * q) = v;
            }
        }
        __syncthreads();

        // ---- coalesced gamma store: GR -> global (contiguous tile) ----
        {
            float* gdst = gamma_out + (size_t)t0 * KCL;
            const int vf = vpts * KCL;
            #pragma unroll
            for (int c = 0; c < 16; ++c) {
                int o4 = c * 256 + tid;
                if (4 * o4 < vf) {
                    float4 v = *(const float4*)(GRf + (o4 >> 4) * 72 + 4 * (o4 & 15));
                    *(float4*)(gdst + 4 * o4) = v;
                }
            }
        }

        // ---- GEMM2: 4 clusters x p-half per thread, 32 pts per warp ----
        {
            #pragma unroll 2
            for (int u = 0; u < 32; ++u) {
                const int pt = q3 * 32 + u;
                const ulonglong2* ap = (const ulonglong2*)(ASMu + pt * 18 + ph * 8);
                ulonglong2 A0 = ap[0], A1 = ap[1], A2 = ap[2], A3 = ap[3];
                ull ar[8] = {A0.x, A0.y, A1.x, A1.y, A2.x, A2.y, A3.x, A3.y};
                float4 g4 = *(const float4*)(GRf + pt * 72 + c4 * 4);
                float gg[4] = {g4.x, g4.y, g4.z, g4.w};
                #pragma unroll
                for (int c = 0; c < 4; ++c) {
                    ull g2 = pk2(gg[c], gg[c]);
                    #pragma unroll
                    for (int j = 0; j < 8; ++j)
                        macc[c][j] = fma2(g2, ar[j], macc[c][j]);
                }
                if (ph == 0) {
                    ull en = pk2(ECs[pt], NAs[pt]);
                    #pragma unroll
                    for (int c = 0; c < 4; ++c) {
                        nacc[c] += gg[c];
                        es2[c] = fma2(pk2(gg[c], gg[c]), en, es2[c]);
                    }
                }
            }
        }
    }

    // ---- combine partials across the 8 point-groups (reuse smem) ----
    __syncthreads();
    ull*   SB = (ull*)sm;                    // 256*32 ull = 64 KB
    float* SN = (float*)(sm + 65536);        // 512 floats
    float* SE = SN + 512;
    float* SS = SE + 512;
    #pragma unroll
    for (int c = 0; c < 4; ++c)
        #pragma unroll
        for (int j = 0; j < 8; ++j)
            SB[tid * 32 + c * 8 + j] = macc[c][j];
    if (ph == 0) {
        int b = q3 * 64 + c4 * 4;
        #pragma unroll
        for (int c = 0; c < 4; ++c) {
            float e, s2; upk2(es2[c], e, s2);
            SN[b + c] = nacc[c]; SE[b + c] = e; SS[b + c] = s2;
        }
    }
    __syncthreads();

    float* my = g_scratch + (size_t)blockIdx.x * NENT;
    for (int o = tid; o < 1024; o += 256) {
        int k = o >> 4, jp = o & 15;
        int cc = k >> 2, c = k & 3, hh = jp >> 3, j = jp & 7;
        float s0 = 0.f, s1 = 0.f;
        #pragma unroll
        for (int q = 0; q < 8; ++q) {
            float x0, x1;
            upk2(SB[(q * 32 + cc * 2 + hh) * 32 + c * 8 + j], x0, x1);
            s0 += x0; s1 += x1;
        }
        my[k * PD + 2 * jp]     = s0;
        my[k * PD + 2 * jp + 1] = s1;
    }
    if (tid < KCL) {
        float n = 0.f, e = 0.f, s2 = 0.f;
        #pragma unroll
        for (int q = 0; q < 8; ++q) {
            n += SN[q * 64 + tid]; e += SE[q * 64 + tid]; s2 += SS[q * 64 + tid];
        }
        my[2048 + tid] = n;
        my[2112 + tid] = e;
        my[2176 + tid] = s2;
    }
}

// Stage 1: reduce g_scratch[nblk][NENT] -> g_acc[NENT], coalesced + MLP=4.
__global__ __launch_bounds__(256)
void deeplpm_reduce(int nblk) {
    int e = blockIdx.x * 256 + threadIdx.x;
    if (e >= NENT) return;
    const float* p = g_scratch + e;
    float s0 = 0.f, s1 = 0.f, s2 = 0.f, s3 = 0.f;
    int b = 0;
    for (; b + 4 <= nblk; b += 4) {
        s0 += p[(size_t)(b + 0) * NENT];
        s1 += p[(size_t)(b + 1) * NENT];
        s2 += p[(size_t)(b + 2) * NENT];
        s3 += p[(size_t)(b + 3) * NENT];
    }
    for (; b < nblk; ++b) s0 += p[(size_t)b * NENT];
    g_acc[e] = (s0 + s1) + (s2 + s3);
}

// Stage 2: final per-cluster math.
__global__ __launch_bounds__(64)
void deeplpm_finalize(float* __restrict__ pi_out,
                      float* __restrict__ mu_out,
                      float* __restrict__ lc_out,
                      int N) {
    int t = threadIdx.x;
    if (t >= KCL) return;
    float Nk = g_acc[2048 + t];
    float Ek = g_acc[2112 + t];
    float Sk = g_acc[2176 + t];
    pi_out[t] = Nk / (float)N;
    float inv = 1.0f / Nk;
    float nm2 = 0.0f;
    #pragma unroll
    for (int p = 0; p < PD; ++p) {
        float m = g_acc[t * PD + p] * inv;
        mu_out[t * PD + p] = m;
        nm2 = fmaf(m, m, nm2);
    }
    float cov = (32.0f * Ek + Sk - Nk * nm2) / (32.0f * Nk);
    lc_out[t] = logf(cov);
}

extern "C" void kernel_launch(void* const* d_in, const int* in_sizes, int n_in,
                              void* d_out, int out_size) {
    const float* mu_phi = (const float*)d_in[0];
    const float* lcp    = (const float*)d_in[1];
    const float* pi_k   = (const float*)d_in[2];
    const float* mu_k   = (const float*)d_in[3];
    const float* lck    = (const float*)d_in[4];
    const int N = in_sizes[0] / PD;

    float* out     = (float*)d_out;
    float* gamma_o = out;
    float* pi_o    = out + (size_t)N * KCL;
    float* mu_o    = pi_o + KCL;
    float* lc_o    = mu_o + KCL * PD;

    int tiles = (N + TILE - 1) / TILE;
    int grid  = tiles < NBLK ? tiles : NBLK;

    cudaFuncSetAttribute(deeplpm_main,
                         cudaFuncAttributeMaxDynamicSharedMemorySize, SMEM_BYTES);

    deeplpm_main<<<grid, 256, SMEM_BYTES>>>(mu_phi, lcp, pi_k, mu_k, lck,
                                            gamma_o, N);
    deeplpm_reduce<<<(NENT + 255) / 256, 256>>>(grid);
    deeplpm_finalize<<<1, 64>>>(pi_o, mu_o, lc_o, N);
}